// round 4
// baseline (speedup 1.0000x reference)
#include <cuda_runtime.h>

#define NN   10000
#define EE   320000
#define FDIM 256
#define CDIM 40

// ---------------- scratch (device globals; no allocation allowed) ----------------
__device__ int   g_is64;
__device__ int   g_deg[NN];
__device__ int   g_rowptr[NN + 1];
__device__ int   g_cursor[NN];
__device__ float g_dinv[NN];
__device__ int   g_col[EE];
__device__ float g_wn[EE];
__device__ __align__(16) float g_hA[NN * FDIM];
__device__ __align__(16) float g_hB[NN * FDIM];
__device__ __align__(16) float g_hw[NN * FDIM];
__device__ __align__(16) float g_hw40[NN * CDIM];
__device__ __align__(16) float g_logits[NN * CDIM];

// device-side buffer selector (no host-side symbol address needed)
__device__ __forceinline__ float* buf(int id) {
    switch (id) {
        case 0: return g_hA;
        case 1: return g_hB;
        case 2: return g_hw;
        case 3: return g_hw40;
        case 4: return g_logits;
    }
    return nullptr;
}

// width-dispatching edge index read: i-th element of edge_index flat buffer
__device__ __forceinline__ int eidx(const void* ei, int i) {
    if (g_is64) return (int)((const long long*)ei)[i];
    return ((const int*)ei)[i];
}

// ---------------- dtype detection + graph preprocessing ----------------
__global__ void init_kernel() {
    int i = blockIdx.x * blockDim.x + threadIdx.x;
    if (i < NN) g_deg[i] = 1;   // self-loop
    if (i == 0) g_is64 = 1;     // assume int64 until disproven
}

// Scan first 320000 odd 32-bit words (always within buffer for either dtype:
// int32 buffer = 640000 words, int64 buffer = 1280000 words).
// int64 with non-negative ids -> all odd words are zero. int32 -> random ids.
__global__ void detect_kernel(const unsigned* __restrict__ w) {
    int i = blockIdx.x * blockDim.x + threadIdx.x;
    if (i < EE) {
        if (w[2 * i + 1] != 0u) g_is64 = 0;
    }
}

__global__ void count_deg_kernel(const void* __restrict__ ei) {
    int e = blockIdx.x * blockDim.x + threadIdx.x;
    if (e < EE) {
        int d = eidx(ei, EE + e);
        if (d >= 0 && d < NN) atomicAdd(&g_deg[d], 1);
    }
}

// single-block exclusive scan of (deg-1) -> rowptr/cursor; also dinv = rsqrt(deg)
__global__ void scan_kernel() {
    const int ITEMS = 10;               // 1024 * 10 >= NN
    __shared__ int wsum[32];
    int t = threadIdx.x;
    int base = t * ITEMS;
    int local[ITEMS];
    int sum = 0;
#pragma unroll
    for (int i = 0; i < ITEMS; i++) {
        int idx = base + i;
        int v = (idx < NN) ? (g_deg[idx] - 1) : 0;
        local[i] = sum;
        sum += v;
    }
    int lane = t & 31, wid = t >> 5;
    int x = sum;
#pragma unroll
    for (int off = 1; off < 32; off <<= 1) {
        int y = __shfl_up_sync(0xffffffffu, x, off);
        if (lane >= off) x += y;
    }
    if (lane == 31) wsum[wid] = x;
    __syncthreads();
    if (wid == 0) {
        int w = wsum[lane];
#pragma unroll
        for (int off = 1; off < 32; off <<= 1) {
            int y = __shfl_up_sync(0xffffffffu, w, off);
            if (lane >= off) w += y;
        }
        wsum[lane] = w;
    }
    __syncthreads();
    int off0 = (x - sum) + (wid > 0 ? wsum[wid - 1] : 0);
#pragma unroll
    for (int i = 0; i < ITEMS; i++) {
        int idx = base + i;
        if (idx < NN) {
            int rp = off0 + local[i];
            g_rowptr[idx] = rp;
            g_cursor[idx] = rp;
            g_dinv[idx]   = rsqrtf((float)g_deg[idx]);
        }
    }
    if (t == 1023) g_rowptr[NN] = off0 + sum;
}

__global__ void fill_kernel(const void* __restrict__ ei) {
    int e = blockIdx.x * blockDim.x + threadIdx.x;
    if (e < EE) {
        int s = eidx(ei, e);
        int d = eidx(ei, EE + e);
        if (s >= 0 && s < NN && d >= 0 && d < NN) {
            int pos = atomicAdd(&g_cursor[d], 1);
            g_col[pos] = s;
            g_wn[pos]  = g_dinv[s] * g_dinv[d];
        }
    }
}

// ---------------- fp32 GEMM: C[M,Nn] = A[M,K] @ W[K,Nn] ----------------
// BM=128, BN=64, BK=16, 256 threads, 8x4 microtile
#define BM 128
#define BN 64
#define BK 16

__global__ __launch_bounds__(256) void gemm_kernel(
    const float* __restrict__ Aext, int a_id,
    const float* __restrict__ W, int c_id,
    int M, int K, int Nn)
{
    const float* A = (a_id < 0) ? Aext : buf(a_id);
    float* C = buf(c_id);

    __shared__ float As[BK][BM + 4];
    __shared__ float Bs[BK][BN + 4];
    int tid = threadIdx.x;
    int bm = blockIdx.y * BM;
    int bn = blockIdx.x * BN;
    int tx = tid & 15;      // n-group
    int ty = tid >> 4;      // m-group
    int ar = tid >> 2;            // 0..63
    int ac = (tid & 3) * 4;       // 0,4,8,12
    int br = tid >> 4;            // 0..15
    int bc = (tid & 15) * 4;      // 0..60

    float acc[8][4];
#pragma unroll
    for (int i = 0; i < 8; i++)
#pragma unroll
        for (int j = 0; j < 4; j++) acc[i][j] = 0.0f;

    for (int k0 = 0; k0 < K; k0 += BK) {
#pragma unroll
        for (int i = 0; i < 2; i++) {
            int m = bm + ar + i * 64;
            float4 v = make_float4(0.f, 0.f, 0.f, 0.f);
            if (m < M) v = *(const float4*)(A + (size_t)m * K + k0 + ac);
            As[ac + 0][ar + i * 64] = v.x;
            As[ac + 1][ar + i * 64] = v.y;
            As[ac + 2][ar + i * 64] = v.z;
            As[ac + 3][ar + i * 64] = v.w;
        }
        {
            float4 v = make_float4(0.f, 0.f, 0.f, 0.f);
            int n = bn + bc;
            if (n < Nn) v = *(const float4*)(W + (size_t)(k0 + br) * Nn + n);
            *(float4*)&Bs[br][bc] = v;
        }
        __syncthreads();
#pragma unroll
        for (int kk = 0; kk < BK; kk++) {
            float4 a0 = *(const float4*)&As[kk][ty * 8];
            float4 a1 = *(const float4*)&As[kk][ty * 8 + 4];
            float4 b  = *(const float4*)&Bs[kk][tx * 4];
            float av[8] = {a0.x, a0.y, a0.z, a0.w, a1.x, a1.y, a1.z, a1.w};
            float bv[4] = {b.x, b.y, b.z, b.w};
#pragma unroll
            for (int i = 0; i < 8; i++)
#pragma unroll
                for (int j = 0; j < 4; j++)
                    acc[i][j] = fmaf(av[i], bv[j], acc[i][j]);
        }
        __syncthreads();
    }
#pragma unroll
    for (int i = 0; i < 8; i++) {
        int m = bm + ty * 8 + i;
        if (m < M) {
#pragma unroll
            for (int j = 0; j < 4; j++) {
                int n = bn + tx * 4 + j;
                if (n < Nn) C[(size_t)m * Nn + n] = acc[i][j];
            }
        }
    }
}

// ---------------- aggregation (256 feats): warp per node, CSR gather ----------------
// reads g_hw, writes buf(out_id)
__global__ void agg256_kernel(const float* __restrict__ bias, int out_id, int relu)
{
    int node = (blockIdx.x * blockDim.x + threadIdx.x) >> 5;
    if (node >= NN) return;
    const float* hw = g_hw;
    float* out = buf(out_id);
    int lane = threadIdx.x & 31;
    int beg = g_rowptr[node], end = g_rowptr[node + 1];

    float dv = g_dinv[node];
    float wself = dv * dv;
    const float4* hp = (const float4*)(hw + (size_t)node * FDIM);
    float4 v0 = hp[lane];
    float4 v1 = hp[lane + 32];
    float4 a0 = make_float4(wself * v0.x, wself * v0.y, wself * v0.z, wself * v0.w);
    float4 a1 = make_float4(wself * v1.x, wself * v1.y, wself * v1.z, wself * v1.w);

#pragma unroll 4
    for (int e = beg; e < end; e++) {
        int s = g_col[e];
        float w = g_wn[e];
        const float4* p = (const float4*)(hw + (size_t)s * FDIM);
        float4 u0 = p[lane];
        float4 u1 = p[lane + 32];
        a0.x = fmaf(w, u0.x, a0.x); a0.y = fmaf(w, u0.y, a0.y);
        a0.z = fmaf(w, u0.z, a0.z); a0.w = fmaf(w, u0.w, a0.w);
        a1.x = fmaf(w, u1.x, a1.x); a1.y = fmaf(w, u1.y, a1.y);
        a1.z = fmaf(w, u1.z, a1.z); a1.w = fmaf(w, u1.w, a1.w);
    }
    const float4* bp = (const float4*)bias;
    float4 b0 = bp[lane], b1 = bp[lane + 32];
    a0.x += b0.x; a0.y += b0.y; a0.z += b0.z; a0.w += b0.w;
    a1.x += b1.x; a1.y += b1.y; a1.z += b1.z; a1.w += b1.w;
    if (relu) {
        a0.x = fmaxf(a0.x, 0.f); a0.y = fmaxf(a0.y, 0.f);
        a0.z = fmaxf(a0.z, 0.f); a0.w = fmaxf(a0.w, 0.f);
        a1.x = fmaxf(a1.x, 0.f); a1.y = fmaxf(a1.y, 0.f);
        a1.z = fmaxf(a1.z, 0.f); a1.w = fmaxf(a1.w, 0.f);
    }
    float4* op = (float4*)(out + (size_t)node * FDIM);
    op[lane]      = a0;
    op[lane + 32] = a1;
}

// ---------------- aggregation (40 feats): warp per node ----------------
// reads g_hw40, writes g_logits
__global__ void agg40_kernel(const float* __restrict__ bias)
{
    int node = (blockIdx.x * blockDim.x + threadIdx.x) >> 5;
    if (node >= NN) return;
    const float* hw = g_hw40;
    float* out = g_logits;
    int lane = threadIdx.x & 31;
    int beg = g_rowptr[node], end = g_rowptr[node + 1];

    float dv = g_dinv[node];
    float wself = dv * dv;
    const float* hp = hw + (size_t)node * CDIM;
    float a0 = (lane < CDIM) ? wself * hp[lane] : 0.f;
    float a1 = (lane + 32 < CDIM) ? wself * hp[lane + 32] : 0.f;

    for (int e = beg; e < end; e++) {
        int s = g_col[e];
        float w = g_wn[e];
        const float* p = hw + (size_t)s * CDIM;
        if (lane < CDIM) a0 = fmaf(w, p[lane], a0);
        if (lane + 32 < CDIM) a1 = fmaf(w, p[lane + 32], a1);
    }
    if (lane < CDIM) a0 += bias[lane];
    if (lane + 32 < CDIM) a1 += bias[lane + 32];
    float* op = out + (size_t)node * CDIM;
    if (lane < CDIM) op[lane] = a0;
    if (lane + 32 < CDIM) op[lane + 32] = a1;
}

// ---------------- log_softmax over 40 classes: warp per node ----------------
__global__ void lsm_kernel(float* __restrict__ out, int write_logits)
{
    int node = (blockIdx.x * blockDim.x + threadIdx.x) >> 5;
    if (node >= NN) return;
    int lane = threadIdx.x & 31;
    const float* lp = g_logits + (size_t)node * CDIM;
    float v0 = lp[lane];                          // lane < 32 < 40 always valid
    float v1 = (lane < CDIM - 32) ? lp[lane + 32] : -1e30f;
    float m = fmaxf(v0, v1);
#pragma unroll
    for (int off = 16; off > 0; off >>= 1)
        m = fmaxf(m, __shfl_xor_sync(0xffffffffu, m, off));
    float s = __expf(v0 - m) + ((lane < CDIM - 32) ? __expf(v1 - m) : 0.f);
#pragma unroll
    for (int off = 16; off > 0; off >>= 1)
        s += __shfl_xor_sync(0xffffffffu, s, off);
    float lse = m + __logf(s);
    float* op = out + (size_t)node * CDIM;
    op[lane] = v0 - lse;
    if (lane < CDIM - 32) op[lane + 32] = v1 - lse;
    if (write_logits) {
        float* lo = out + (size_t)NN * CDIM + (size_t)node * CDIM;
        lo[lane] = v0;
        if (lane < CDIM - 32) lo[lane + 32] = v1;
    }
}

// ---------------- host ----------------
extern "C" void kernel_launch(void* const* d_in, const int* in_sizes, int n_in,
                              void* d_out, int out_size)
{
    const float* x  = (const float*)d_in[0];
    const void*  ei = d_in[1];
    const float* W1 = (const float*)d_in[2];  const float* b1 = (const float*)d_in[3];
    const float* W2 = (const float*)d_in[4];  const float* b2 = (const float*)d_in[5];
    const float* W3 = (const float*)d_in[6];  const float* b3 = (const float*)d_in[7];
    const float* W4 = (const float*)d_in[8];  const float* b4 = (const float*)d_in[9];
    const float* W5 = (const float*)d_in[10]; const float* b5 = (const float*)d_in[11];
    float* out = (float*)d_out;

    const int EB = (EE + 255) / 256;
    const int AGGB = (NN * 32 + 255) / 256;  // warp per node

    init_kernel<<<(NN + 255) / 256, 256>>>();
    detect_kernel<<<EB, 256>>>((const unsigned*)ei);
    count_deg_kernel<<<EB, 256>>>(ei);
    scan_kernel<<<1, 1024>>>();
    fill_kernel<<<EB, 256>>>(ei);

    dim3 g256((FDIM + BN - 1) / BN, (NN + BM - 1) / BM);   // (4, 79)
    dim3 g40((CDIM + BN - 1) / BN, (NN + BM - 1) / BM);    // (1, 79)

    // buffer ids: 0=g_hA, 1=g_hB, 2=g_hw, 3=g_hw40, 4=g_logits
    // layer 1: x @ W1 -> hw ; agg -> hA
    gemm_kernel<<<g256, 256>>>(x, -1, W1, 2, NN, FDIM, FDIM);
    agg256_kernel<<<AGGB, 256>>>(b1, 0, 1);
    // layer 2: hA @ W2 -> hw ; agg -> hB
    gemm_kernel<<<g256, 256>>>(nullptr, 0, W2, 2, NN, FDIM, FDIM);
    agg256_kernel<<<AGGB, 256>>>(b2, 1, 1);
    // layer 3: hB @ W3 -> hw ; agg -> hA
    gemm_kernel<<<g256, 256>>>(nullptr, 1, W3, 2, NN, FDIM, FDIM);
    agg256_kernel<<<AGGB, 256>>>(b3, 0, 1);
    // layer 4: hA @ W4 -> hw ; agg -> hB
    gemm_kernel<<<g256, 256>>>(nullptr, 0, W4, 2, NN, FDIM, FDIM);
    agg256_kernel<<<AGGB, 256>>>(b4, 1, 1);
    // layer 5: hB @ W5 -> hw40 ; agg -> logits ; log_softmax
    gemm_kernel<<<g40, 256>>>(nullptr, 1, W5, 3, NN, FDIM, CDIM);
    agg40_kernel<<<AGGB, 256>>>(b5);
    int write_logits = (out_size >= 2 * NN * CDIM) ? 1 : 0;
    lsm_kernel<<<AGGB, 256>>>(out, write_logits);

    (void)in_sizes; (void)n_in;
}